// round 7
// baseline (speedup 1.0000x reference)
#include <cuda_runtime.h>
#include <cstdint>
#include <math.h>

// LSTM_2370821948014 — round 6: mma.sync tf32; N=512 gate tiles (warp tile
// 32x64), k16 tiles, NBUF=3 prefetch distance 2, hoisted swizzle constants.
//
// B=65536, I=128, H=256, O=256, K=384.
// w_packed layout: 48 gate tiles (2 passes x 24 k-tiles, 512 rows x 16 k,
// 32KB) then 24 logits tiles (256 rows x 16 k, 16KB). Row stride 16 u32,
// element (v,kw) at kw ^ (((v>>1)&3)<<2)  (conflict-free for mma B reads).
// Gate tile row v = wn*64 + (g*2+jh)*8 + jlo -> w_i2h row
//   g*256 + p*128 + wn*16 + jh*8 + jlo   (all 4 gates land in one thread).

static constexpr int BATCH = 65536;
static constexpr int ODIM  = 256;
static constexpr int KDIM  = 384;
static constexpr int MT    = 64;
static constexpr int THREADS = 512;
static constexpr int NBUF = 3;
static constexpr int NT_G = 48;            // gate tiles
static constexpr int NT_ALL = 72;          // + 24 logits tiles
static constexpr int GT_U32 = 8192;        // 512*16
static constexpr int LT_U32 = 4096;        // 256*16
static constexpr int LOG_BASE = NT_G * GT_U32;   // 393216

// SMEM layout (bytes)
static constexpr int PA      = 388;                 // A pitch (u32)
static constexpr int SM_A    = 0;                   // 99328
static constexpr int SM_W    = 99328;               // 3 x 32768
static constexpr int WB      = 32768;
static constexpr int SM_BIAS = SM_W + NBUF * WB;    // 197632 (1280 floats)
static constexpr int SM_REDM = SM_BIAS + 5120;      // 202752
static constexpr int SM_REDS = SM_REDM + 2048;      // 204800
static constexpr int SM_MB   = SM_REDS + 2048;      // 206848
static constexpr int SMEM_TOTAL = SM_MB + 32;       // 206880

__device__ uint32_t w_packed[LOG_BASE + 24 * LT_U32];   // 1.97MB

// ---------------- helpers ----------------

__device__ __forceinline__ uint32_t smem_u32(const void* p) {
    uint32_t a;
    asm("{ .reg .u64 t; cvta.to.shared.u64 t, %1; cvt.u32.u64 %0, t; }"
        : "=r"(a) : "l"(p));
    return a;
}

__device__ __forceinline__ uint32_t f2tf(float x) {
    uint32_t u;
    asm("cvt.rna.tf32.f32 %0, %1;" : "=r"(u) : "f"(x));
    return u;
}

__device__ __forceinline__ void mbar_init(uint32_t a) {
    asm volatile("mbarrier.init.shared.b64 [%0], %1;" :: "r"(a), "r"(1u) : "memory");
}

__device__ __forceinline__ void mbar_expect_tx(uint32_t a, uint32_t bytes) {
    asm volatile("mbarrier.arrive.expect_tx.shared.b64 _, [%0], %1;"
                 :: "r"(a), "r"(bytes) : "memory");
}

__device__ __forceinline__ void mbar_wait(uint32_t a, uint32_t parity) {
    asm volatile(
        "{\n\t"
        ".reg .pred P;\n\t"
        "W%=:\n\t"
        "mbarrier.try_wait.parity.acquire.cta.shared::cta.b64 P, [%0], %1, 0x989680;\n\t"
        "@P bra D%=;\n\t"
        "bra W%=;\n\t"
        "D%=:\n\t"
        "}"
        :: "r"(a), "r"(parity) : "memory");
}

__device__ __forceinline__ void bulk_ld(uint32_t dst, const void* src,
                                        uint32_t bytes, uint32_t mbar) {
    asm volatile(
        "cp.async.bulk.shared::cluster.global.mbarrier::complete_tx::bytes "
        "[%0], [%1], %2, [%3];"
        :: "r"(dst), "l"(src), "r"(bytes), "r"(mbar) : "memory");
}

__device__ __forceinline__ void mma8(float* d, const uint32_t* a,
                                     uint32_t b0, uint32_t b1) {
    asm volatile(
        "mma.sync.aligned.m16n8k8.row.col.f32.tf32.tf32.f32 "
        "{%0,%1,%2,%3}, {%4,%5,%6,%7}, {%8,%9}, {%0,%1,%2,%3};"
        : "+f"(d[0]), "+f"(d[1]), "+f"(d[2]), "+f"(d[3])
        : "r"(a[0]), "r"(a[1]), "r"(a[2]), "r"(a[3]), "r"(b0), "r"(b1));
}

__device__ __forceinline__ float sigf(float x) {
    return 1.0f / (1.0f + __expf(-x));
}
__device__ __forceinline__ float tanh_fast(float x) {
    x = fminf(fmaxf(x, -15.0f), 15.0f);
    float e = __expf(2.0f * x);
    return (e - 1.0f) / (e + 1.0f);
}

// ---------------- repack kernel ----------------

__global__ void repack_kernel(const float* __restrict__ w_i2h,
                              const float* __restrict__ w_i2o)
{
    int i = blockIdx.x * 256 + threadIdx.x;
    if (i >= LOG_BASE + 24 * LT_U32) return;
    int v, kw, row, k;
    const float* src;
    uint32_t dst;
    if (i < LOG_BASE) {
        int t = i >> 13;          // gate tile 0..47
        int e = i & 8191;
        v  = e >> 4;              // 0..511
        kw = e & 15;
        int p  = t / 24;
        int kk = t - p * 24;
        int wn  = v >> 6;
        int r6  = v & 63;
        int nt  = r6 >> 3;
        int jlo = v & 7;
        int g   = nt >> 1;
        int jh  = nt & 1;
        row = g * 256 + p * 128 + wn * 16 + jh * 8 + jlo;
        k   = kk * 16 + kw;
        src = w_i2h;
        dst = t * GT_U32;
    } else {
        int j = i - LOG_BASE;
        int t = j >> 12;          // logits tile 0..23
        int e = j & 4095;
        v  = e >> 4;              // 0..255
        kw = e & 15;
        row = v;
        k   = t * 16 + kw;
        src = w_i2o;
        dst = LOG_BASE + t * LT_U32;
    }
    float x = src[(size_t)row * KDIM + k];
    w_packed[dst + v * 16 + (kw ^ (((v >> 1) & 3) << 2))] = f2tf(x);
}

// ---------------- main kernel ----------------

__global__ __launch_bounds__(THREADS, 1)
void lstm_mma_kernel(const float* __restrict__ input,
                     const float* __restrict__ hidden,
                     const float* __restrict__ b_i2h,
                     const float* __restrict__ b_i2o,
                     float* __restrict__ out)
{
    extern __shared__ char smem[];
    const uint32_t sbase = smem_u32(smem);
    const int tid  = threadIdx.x;
    const int wid  = tid >> 5;
    const int lane = tid & 31;
    const int wm   = wid >> 3;          // 0..1 (M)
    const int wn   = wid & 7;           // 0..7 (N)
    const int gID  = lane >> 2;         // 0..7
    const int lq   = lane & 3;          // 0..3
    const int rbase = blockIdx.x * MT;

    // hoisted B-load offsets (per-thread constants)
    const int sw2 = ((gID >> 1) & 3) << 2;
    const int o00 = (0 + lq) ^ sw2;          // ks0 b0
    const int o01 = (4 + lq) ^ sw2;          // ks0 b1
    const int o10 = (8 + lq) ^ sw2;          // ks1 b0
    const int o11 = (12 + lq) ^ sw2;         // ks1 b1
    const int wgB = wn * 1024 + gID * 16;    // gates tile base (u32)
    const int wlB = wn * 512  + gID * 16;    // logits tile base

    uint32_t* Au = (uint32_t*)(smem + SM_A);
    float*    Af = (float*)(smem + SM_A);
    float*    bias = (float*)(smem + SM_BIAS);

    if (tid == 0)
        for (int b = 0; b < NBUF; ++b) mbar_init(sbase + SM_MB + 8 * b);
    __syncthreads();

    // prologue: issue tiles 0,1 (overlaps A/bias staging)
    if (tid == 0) {
        mbar_expect_tx(sbase + SM_MB, WB);
        bulk_ld(sbase + SM_W, w_packed, WB, sbase + SM_MB);
        mbar_expect_tx(sbase + SM_MB + 8, WB);
        bulk_ld(sbase + SM_W + WB, w_packed + GT_U32, WB, sbase + SM_MB + 8);
    }

    // stage A = [input | hidden], tf32, pitch 388
    for (int idx = tid; idx < MT * 96; idx += THREADS) {
        int r  = idx / 96;
        int c4 = idx - r * 96;
        float4 v = (c4 < 32)
            ? *(const float4*)(input  + (size_t)(rbase + r) * 128 + c4 * 4)
            : *(const float4*)(hidden + (size_t)(rbase + r) * 256 + (c4 - 32) * 4);
        uint4 u;
        u.x = f2tf(v.x); u.y = f2tf(v.y); u.z = f2tf(v.z); u.w = f2tf(v.w);
        *(uint4*)(Au + r * PA + c4 * 4) = u;
    }
    for (int i = tid; i < 1280; i += THREADS)
        bias[i] = (i < 1024) ? b_i2h[i] : b_i2o[i - 1024];
    __syncthreads();

    float* outLS = out;
    float* outNH = out + (size_t)BATCH * ODIM;

    float acc[2][8][4];
    #pragma unroll
    for (int m = 0; m < 2; ++m)
        #pragma unroll
        for (int n = 0; n < 8; ++n)
            #pragma unroll
            for (int c = 0; c < 4; ++c) acc[m][n][c] = 0.0f;

    const int ra0 = (wm * 32 + gID) * PA;       // rows gID / +8
    const int ra1 = (wm * 32 + 16 + gID) * PA;  // rows +16 / +24

    for (int t = 0; t < NT_ALL; ++t) {
        const int buf = t % NBUF;
        // prefetch t+2 (its buffer's last consumer was t-1, retired at the
        // previous __syncthreads)
        if (t + 2 < NT_ALL && tid == 0) {
            int nt2 = t + 2;
            int nb  = nt2 % NBUF;
            uint32_t mb = sbase + SM_MB + 8 * nb;
            const uint32_t* src = (nt2 < NT_G)
                ? (w_packed + (size_t)nt2 * GT_U32)
                : (w_packed + LOG_BASE + (size_t)(nt2 - NT_G) * LT_U32);
            uint32_t bytes = (nt2 < NT_G) ? 32768u : 16384u;
            mbar_expect_tx(mb, bytes);
            bulk_ld(sbase + SM_W + nb * WB, src, bytes, mb);
        }
        mbar_wait(sbase + SM_MB + 8 * buf, (t / NBUF) & 1);

        const uint32_t* Wu = (const uint32_t*)(smem + SM_W + buf * WB);

        if (t < NT_G) {
            // ---- gates tile: 512 rows x 16 k, warp tile 32x64 ----
            const int k0 = (t % 24) * 16;
            #pragma unroll
            for (int ks = 0; ks < 2; ++ks) {
                const int ka = k0 + ks * 8;
                uint32_t a0[4], a1[4];
                a0[0] = Au[ra0 + ka + lq];
                a0[1] = Au[ra0 + 8 * PA + ka + lq];
                a0[2] = Au[ra0 + ka + lq + 4];
                a0[3] = Au[ra0 + 8 * PA + ka + lq + 4];
                a1[0] = Au[ra1 + ka + lq];
                a1[1] = Au[ra1 + 8 * PA + ka + lq];
                a1[2] = Au[ra1 + ka + lq + 4];
                a1[3] = Au[ra1 + 8 * PA + ka + lq + 4];
                const int ob0 = ks ? o10 : o00;
                const int ob1 = ks ? o11 : o01;
                #pragma unroll
                for (int nt = 0; nt < 8; ++nt) {
                    uint32_t b0 = Wu[wgB + nt * 128 + ob0];
                    uint32_t b1 = Wu[wgB + nt * 128 + ob1];
                    mma8(acc[0][nt], a0, b0, b1);
                    mma8(acc[1][nt], a1, b0, b1);
                }
            }

            if ((t % 24) == 23) {
                // ---- LSTM epilogue, pass p ----
                const int p = t / 24;
                #pragma unroll
                for (int mt = 0; mt < 2; ++mt)
                    #pragma unroll
                    for (int rh = 0; rh < 2; ++rh)
                        #pragma unroll
                        for (int jh = 0; jh < 2; ++jh) {
                            int r  = wm * 32 + mt * 16 + rh * 8 + gID;
                            int j0 = p * 128 + wn * 16 + jh * 8 + lq * 2;
                            int ci = rh * 2;
                            float h0 = acc[mt][jh][ci]     + bias[j0];
                            float h1 = acc[mt][jh][ci+1]   + bias[j0+1];
                            float i0 = acc[mt][2+jh][ci]   + bias[256+j0];
                            float i1 = acc[mt][2+jh][ci+1] + bias[256+j0+1];
                            float f0 = acc[mt][4+jh][ci]   + bias[512+j0];
                            float f1 = acc[mt][4+jh][ci+1] + bias[512+j0+1];
                            float o0 = acc[mt][6+jh][ci]   + bias[768+j0];
                            float o1 = acc[mt][6+jh][ci+1] + bias[768+j0+1];
                            float hv0 = Af[r * PA + 128 + j0];
                            float hv1 = Af[r * PA + 128 + j0 + 1];
                            float2 nh;
                            nh.x = sigf(o0) * tanh_fast(sigf(f0) * hv0 + sigf(i0) * tanh_fast(h0));
                            nh.y = sigf(o1) * tanh_fast(sigf(f1) * hv1 + sigf(i1) * tanh_fast(h1));
                            *(float2*)(outNH + (size_t)(rbase + r) * 256 + j0) = nh;
                        }
                #pragma unroll
                for (int m = 0; m < 2; ++m)
                    #pragma unroll
                    for (int n = 0; n < 8; ++n)
                        #pragma unroll
                        for (int c = 0; c < 4; ++c) acc[m][n][c] = 0.0f;
            }
        } else {
            // ---- logits tile: 256 rows x 16 k, warp tile 32x32 ----
            const int k0 = (t - NT_G) * 16;
            #pragma unroll
            for (int ks = 0; ks < 2; ++ks) {
                const int ka = k0 + ks * 8;
                uint32_t a0[4], a1[4];
                a0[0] = Au[ra0 + ka + lq];
                a0[1] = Au[ra0 + 8 * PA + ka + lq];
                a0[2] = Au[ra0 + ka + lq + 4];
                a0[3] = Au[ra0 + 8 * PA + ka + lq + 4];
                a1[0] = Au[ra1 + ka + lq];
                a1[1] = Au[ra1 + 8 * PA + ka + lq];
                a1[2] = Au[ra1 + ka + lq + 4];
                a1[3] = Au[ra1 + 8 * PA + ka + lq + 4];
                const int ob0 = ks ? o10 : o00;
                const int ob1 = ks ? o11 : o01;
                #pragma unroll
                for (int nt = 0; nt < 4; ++nt) {
                    uint32_t b0 = Wu[wlB + nt * 128 + ob0];
                    uint32_t b1 = Wu[wlB + nt * 128 + ob1];
                    mma8(acc[0][nt], a0, b0, b1);
                    mma8(acc[1][nt], a1, b0, b1);
                }
            }

            if (t == NT_ALL - 1) {
                // ---- logits epilogue: log_softmax over 256 cols ----
                float* redm = (float*)(smem + SM_REDM);
                float* reds = (float*)(smem + SM_REDS);

                #pragma unroll
                for (int mt = 0; mt < 2; ++mt)
                    #pragma unroll
                    for (int nt = 0; nt < 4; ++nt) {
                        int n0 = wn * 32 + nt * 8 + lq * 2;
                        acc[mt][nt][0] += bias[1024 + n0];
                        acc[mt][nt][1] += bias[1024 + n0 + 1];
                        acc[mt][nt][2] += bias[1024 + n0];
                        acc[mt][nt][3] += bias[1024 + n0 + 1];
                    }

                #pragma unroll
                for (int mt = 0; mt < 2; ++mt)
                    #pragma unroll
                    for (int rh = 0; rh < 2; ++rh) {
                        float m = -3.4e38f;
                        #pragma unroll
                        for (int nt = 0; nt < 4; ++nt) {
                            m = fmaxf(m, acc[mt][nt][rh*2]);
                            m = fmaxf(m, acc[mt][nt][rh*2+1]);
                        }
                        m = fmaxf(m, __shfl_xor_sync(0xffffffffu, m, 1));
                        m = fmaxf(m, __shfl_xor_sync(0xffffffffu, m, 2));
                        if (lq == 0) {
                            int r = wm * 32 + mt * 16 + rh * 8 + gID;
                            redm[r * 8 + wn] = m;
                        }
                    }
                __syncthreads();

                float M[2][2], L[2][2];
                #pragma unroll
                for (int mt = 0; mt < 2; ++mt)
                    #pragma unroll
                    for (int rh = 0; rh < 2; ++rh) {
                        int r = wm * 32 + mt * 16 + rh * 8 + gID;
                        const float* rm = redm + r * 8;
                        float m = fmaxf(fmaxf(fmaxf(rm[0], rm[1]),
                                              fmaxf(rm[2], rm[3])),
                                        fmaxf(fmaxf(rm[4], rm[5]),
                                              fmaxf(rm[6], rm[7])));
                        M[mt][rh] = m;
                        float s = 0.0f;
                        #pragma unroll
                        for (int nt = 0; nt < 4; ++nt) {
                            s += __expf(acc[mt][nt][rh*2]   - m);
                            s += __expf(acc[mt][nt][rh*2+1] - m);
                        }
                        s += __shfl_xor_sync(0xffffffffu, s, 1);
                        s += __shfl_xor_sync(0xffffffffu, s, 2);
                        if (lq == 0) reds[r * 8 + wn] = s;
                    }
                __syncthreads();

                #pragma unroll
                for (int mt = 0; mt < 2; ++mt)
                    #pragma unroll
                    for (int rh = 0; rh < 2; ++rh) {
                        int r = wm * 32 + mt * 16 + rh * 8 + gID;
                        const float* rs = reds + r * 8;
                        float st = ((rs[0] + rs[1]) + (rs[2] + rs[3])) +
                                   ((rs[4] + rs[5]) + (rs[6] + rs[7]));
                        L[mt][rh] = M[mt][rh] + logf(st);
                    }

                #pragma unroll
                for (int mt = 0; mt < 2; ++mt)
                    #pragma unroll
                    for (int rh = 0; rh < 2; ++rh) {
                        int r = wm * 32 + mt * 16 + rh * 8 + gID;
                        float lse = L[mt][rh];
                        #pragma unroll
                        for (int nt = 0; nt < 4; ++nt) {
                            int n0 = wn * 32 + nt * 8 + lq * 2;
                            float2 o;
                            o.x = acc[mt][nt][rh*2]   - lse;
                            o.y = acc[mt][nt][rh*2+1] - lse;
                            *(float2*)(outLS + (size_t)(rbase + r) * 256 + n0) = o;
                        }
                    }
            }
        }
        __syncthreads();   // all warps done with this W buffer before reuse
    }
}

extern "C" void kernel_launch(void* const* d_in, const int* in_sizes, int n_in,
                              void* d_out, int out_size)
{
    (void)in_sizes; (void)n_in; (void)out_size;
    const float* input  = (const float*)d_in[0];
    const float* hidden = (const float*)d_in[1];
    const float* w_i2h  = (const float*)d_in[2];
    const float* b_i2h  = (const float*)d_in[3];
    const float* w_i2o  = (const float*)d_in[4];
    const float* b_i2o  = (const float*)d_in[5];
    float* out = (float*)d_out;

    const int total = LOG_BASE + 24 * LT_U32;
    repack_kernel<<<(total + 255) / 256, 256>>>(w_i2h, w_i2o);

    cudaFuncSetAttribute(lstm_mma_kernel,
                         cudaFuncAttributeMaxDynamicSharedMemorySize,
                         SMEM_TOTAL);
    lstm_mma_kernel<<<BATCH / MT, THREADS, SMEM_TOTAL>>>(
        input, hidden, b_i2h, b_i2o, out);
}

// round 8
// speedup vs baseline: 1.4263x; 1.4263x over previous
#include <cuda_runtime.h>
#include <cuda_fp16.h>
#include <cstdint>
#include <math.h>

// LSTM_2370821948014 — round 7: mma.sync.m16n8k16.f16 (full-rate tensor op;
// tf32 m16n8k8 measured saturated at ~8cyc/instr => 522us wall).
// R5 tile structure: 60 tiles of 256 rows x 32 k; warp tile 32x32; 16 warps.
// NBUF=3, prefetch distance 2. A in SMEM as fp16 pairs (pitch 196 u32,
// conflict-free); hidden kept fp32 in SMEM for the epilogue; B tiles fp16
// 16KB with XOR swizzle w ^ (((v>>1)&3)<<2).

static constexpr int BATCH = 65536;
static constexpr int ODIM  = 256;
static constexpr int KDIM  = 384;
static constexpr int MT    = 64;
static constexpr int THREADS = 512;
static constexpr int NBUF = 3;
static constexpr int NTILES  = 60;        // 5 chunks x 12 k-tiles
static constexpr int TILE_U32 = 4096;     // 256 rows x 16 words (16KB)

// SMEM layout (bytes)
static constexpr int PA2     = 196;                 // A pitch (u32, fp16 pairs)
static constexpr int SM_A    = 0;                   // 64*196*4 = 50176
static constexpr int PH      = 260;                 // hidden-f32 pitch (floats)
static constexpr int SM_H    = 50176;               // 64*260*4 = 66560
static constexpr int SM_W    = 116736;              // 3 x 16384
static constexpr int WB      = 16384;
static constexpr int SM_BIAS = SM_W + NBUF * WB;    // 165888 (1280 floats)
static constexpr int SM_REDM = SM_BIAS + 5120;      // 171008
static constexpr int SM_REDS = SM_REDM + 2048;      // 173056
static constexpr int SM_MB   = SM_REDS + 2048;      // 175104
static constexpr int SMEM_TOTAL = SM_MB + 32;       // 175136

__device__ uint32_t w_packed[NTILES * TILE_U32];    // ~0.98MB scratch

// ---------------- helpers ----------------

__device__ __forceinline__ uint32_t smem_u32(const void* p) {
    uint32_t a;
    asm("{ .reg .u64 t; cvta.to.shared.u64 t, %1; cvt.u32.u64 %0, t; }"
        : "=r"(a) : "l"(p));
    return a;
}

__device__ __forceinline__ uint32_t pack_h2(float x, float y) {
    __half2 h = __floats2half2_rn(x, y);
    return *reinterpret_cast<uint32_t*>(&h);
}

__device__ __forceinline__ void mbar_init(uint32_t a) {
    asm volatile("mbarrier.init.shared.b64 [%0], %1;" :: "r"(a), "r"(1u) : "memory");
}

__device__ __forceinline__ void mbar_expect_tx(uint32_t a, uint32_t bytes) {
    asm volatile("mbarrier.arrive.expect_tx.shared.b64 _, [%0], %1;"
                 :: "r"(a), "r"(bytes) : "memory");
}

__device__ __forceinline__ void mbar_wait(uint32_t a, uint32_t parity) {
    asm volatile(
        "{\n\t"
        ".reg .pred P;\n\t"
        "W%=:\n\t"
        "mbarrier.try_wait.parity.acquire.cta.shared::cta.b64 P, [%0], %1, 0x989680;\n\t"
        "@P bra D%=;\n\t"
        "bra W%=;\n\t"
        "D%=:\n\t"
        "}"
        :: "r"(a), "r"(parity) : "memory");
}

__device__ __forceinline__ void bulk_ld(uint32_t dst, const void* src,
                                        uint32_t bytes, uint32_t mbar) {
    asm volatile(
        "cp.async.bulk.shared::cluster.global.mbarrier::complete_tx::bytes "
        "[%0], [%1], %2, [%3];"
        :: "r"(dst), "l"(src), "r"(bytes), "r"(mbar) : "memory");
}

__device__ __forceinline__ void mma16(float* d, const uint32_t* a,
                                      uint32_t b0, uint32_t b1) {
    asm volatile(
        "mma.sync.aligned.m16n8k16.row.col.f32.f16.f16.f32 "
        "{%0,%1,%2,%3}, {%4,%5,%6,%7}, {%8,%9}, {%0,%1,%2,%3};"
        : "+f"(d[0]), "+f"(d[1]), "+f"(d[2]), "+f"(d[3])
        : "r"(a[0]), "r"(a[1]), "r"(a[2]), "r"(a[3]), "r"(b0), "r"(b1));
}

__device__ __forceinline__ float sigf(float x) {
    return 1.0f / (1.0f + __expf(-x));
}
__device__ __forceinline__ float tanh_fast(float x) {
    x = fminf(fmaxf(x, -15.0f), 15.0f);
    float e = __expf(2.0f * x);
    return (e - 1.0f) / (e + 1.0f);
}

// ---------------- repack kernel ----------------
// tile t = chunk*12 + kk.  Gates chunks (0..3): tile row v = wn*32 + g*8 + jlo
//   -> w_i2h row g*256 + chunk*64 + wn*8 + jlo.  Logits chunk (4): row v.
// Word w (0..15) of row v holds fp16 pair (k = kk*32 + 2w, +1), stored at
//   u32 index v*16 + (w ^ (((v>>1)&3)<<2)).

__global__ void repack_kernel(const float* __restrict__ w_i2h,
                              const float* __restrict__ w_i2o)
{
    int i = blockIdx.x * 256 + threadIdx.x;
    if (i >= NTILES * TILE_U32) return;
    int t  = i >> 12;
    int e  = i & 4095;
    int v  = e >> 4;
    int w  = e & 15;
    int chunk = t / 12;
    int kk    = t - chunk * 12;
    const float* src;
    int row;
    if (chunk < 4) {
        int wn  = v >> 5;
        int g   = (v >> 3) & 3;
        int jlo = v & 7;
        row = g * 256 + chunk * 64 + wn * 8 + jlo;
        src = w_i2h;
    } else {
        row = v;
        src = w_i2o;
    }
    const float* p = src + (size_t)row * KDIM + kk * 32 + w * 2;
    w_packed[t * TILE_U32 + v * 16 + (w ^ (((v >> 1) & 3) << 2))] =
        pack_h2(p[0], p[1]);
}

// ---------------- main kernel ----------------

__global__ __launch_bounds__(THREADS, 1)
void lstm_mma_kernel(const float* __restrict__ input,
                     const float* __restrict__ hidden,
                     const float* __restrict__ b_i2h,
                     const float* __restrict__ b_i2o,
                     float* __restrict__ out)
{
    extern __shared__ char smem[];
    const uint32_t sbase = smem_u32(smem);
    const int tid  = threadIdx.x;
    const int wid  = tid >> 5;
    const int lane = tid & 31;
    const int wm   = wid >> 3;          // 0..1 (M)
    const int wn   = wid & 7;           // 0..7 (N)
    const int gID  = lane >> 2;         // 0..7
    const int lq   = lane & 3;          // 0..3
    const int rbase = blockIdx.x * MT;

    // hoisted B-word offsets (swizzle folded in): word w ^ sw2
    const int sw2 = ((gID >> 1) & 3) << 2;
    const int ob00 = (0  + lq) ^ sw2;   // ks0, k 0-7
    const int ob01 = (4  + lq) ^ sw2;   // ks0, k 8-15
    const int ob10 = (8  + lq) ^ sw2;   // ks1, k 0-7
    const int ob11 = (12 + lq) ^ sw2;   // ks1, k 8-15

    uint32_t* Au2 = (uint32_t*)(smem + SM_A);
    float*    Hf  = (float*)(smem + SM_H);
    float*    bias = (float*)(smem + SM_BIAS);

    if (tid == 0)
        for (int b = 0; b < NBUF; ++b) mbar_init(sbase + SM_MB + 8 * b);
    __syncthreads();

    // prologue: issue tiles 0,1 (overlaps A/bias staging)
    if (tid == 0) {
        mbar_expect_tx(sbase + SM_MB, WB);
        bulk_ld(sbase + SM_W, w_packed, WB, sbase + SM_MB);
        mbar_expect_tx(sbase + SM_MB + 8, WB);
        bulk_ld(sbase + SM_W + WB, w_packed + TILE_U32, WB, sbase + SM_MB + 8);
    }

    // stage A (fp16 pairs, pitch 196 u32) + hidden fp32 copy (pitch 260)
    for (int idx = tid; idx < MT * 96; idx += THREADS) {
        int r  = idx / 96;
        int c4 = idx - r * 96;
        float4 v;
        if (c4 < 32) {
            v = *(const float4*)(input + (size_t)(rbase + r) * 128 + c4 * 4);
        } else {
            v = *(const float4*)(hidden + (size_t)(rbase + r) * 256 + (c4 - 32) * 4);
            *(float4*)(Hf + r * PH + (c4 - 32) * 4) = v;
        }
        uint2 u;
        u.x = pack_h2(v.x, v.y);
        u.y = pack_h2(v.z, v.w);
        *(uint2*)(Au2 + r * PA2 + c4 * 2) = u;
    }
    for (int i = tid; i < 1280; i += THREADS)
        bias[i] = (i < 1024) ? b_i2h[i] : b_i2o[i - 1024];
    __syncthreads();

    float* outLS = out;
    float* outNH = out + (size_t)BATCH * ODIM;

    float acc[2][4][4];
    #pragma unroll
    for (int m = 0; m < 2; ++m)
        #pragma unroll
        for (int n = 0; n < 4; ++n)
            #pragma unroll
            for (int c = 0; c < 4; ++c) acc[m][n][c] = 0.0f;

    const int ra0 = (wm * 32 + gID) * PA2;        // rows gID / +8
    const int ra1 = (wm * 32 + 16 + gID) * PA2;   // rows +16 / +24

    for (int t = 0; t < NTILES; ++t) {
        const int buf = t % NBUF;
        // prefetch t+2 (buffer's last consumer was t-1, retired at prev bar)
        if (t + 2 < NTILES && tid == 0) {
            int nb = (t + 2) % NBUF;
            uint32_t mb = sbase + SM_MB + 8 * nb;
            mbar_expect_tx(mb, WB);
            bulk_ld(sbase + SM_W + nb * WB,
                    w_packed + (size_t)(t + 2) * TILE_U32, WB, mb);
        }
        mbar_wait(sbase + SM_MB + 8 * buf, (t / NBUF) & 1);

        const uint32_t* Wu = (const uint32_t*)(smem + SM_W + buf * WB);
        const int ktw = (t % 12) * 16;     // word base in A rows

        #pragma unroll
        for (int ks = 0; ks < 2; ++ks) {
            const int wa = ktw + ks * 8;
            uint32_t a0[4], a1[4];
            a0[0] = Au2[ra0 + wa + lq];
            a0[1] = Au2[ra0 + 8 * PA2 + wa + lq];
            a0[2] = Au2[ra0 + wa + 4 + lq];
            a0[3] = Au2[ra0 + 8 * PA2 + wa + 4 + lq];
            a1[0] = Au2[ra1 + wa + lq];
            a1[1] = Au2[ra1 + 8 * PA2 + wa + lq];
            a1[2] = Au2[ra1 + wa + 4 + lq];
            a1[3] = Au2[ra1 + 8 * PA2 + wa + 4 + lq];
            const int ob0 = ks ? ob10 : ob00;
            const int ob1 = ks ? ob11 : ob01;
            #pragma unroll
            for (int nt = 0; nt < 4; ++nt) {
                const int vr = (wn * 32 + nt * 8 + gID) * 16;
                uint32_t b0 = Wu[vr + ob0];
                uint32_t b1 = Wu[vr + ob1];
                mma16(acc[0][nt], a0, b0, b1);
                mma16(acc[1][nt], a1, b0, b1);
            }
        }

        if ((t % 12) == 11) {
            const int chunk = t / 12;
            if (chunk < 4) {
                // ---- LSTM epilogue: gates g = nt, all in-register ----
                #pragma unroll
                for (int mt = 0; mt < 2; ++mt)
                    #pragma unroll
                    for (int rh = 0; rh < 2; ++rh) {
                        int r  = wm * 32 + mt * 16 + rh * 8 + gID;
                        int j0 = chunk * 64 + wn * 8 + lq * 2;
                        int ci = rh * 2;
                        float h0 = acc[mt][0][ci]   + bias[j0];
                        float h1 = acc[mt][0][ci+1] + bias[j0+1];
                        float i0 = acc[mt][1][ci]   + bias[256+j0];
                        float i1 = acc[mt][1][ci+1] + bias[256+j0+1];
                        float f0 = acc[mt][2][ci]   + bias[512+j0];
                        float f1 = acc[mt][2][ci+1] + bias[512+j0+1];
                        float o0 = acc[mt][3][ci]   + bias[768+j0];
                        float o1 = acc[mt][3][ci+1] + bias[768+j0+1];
                        float hv0 = Hf[r * PH + j0];
                        float hv1 = Hf[r * PH + j0 + 1];
                        float2 nh;
                        nh.x = sigf(o0) * tanh_fast(sigf(f0) * hv0 + sigf(i0) * tanh_fast(h0));
                        nh.y = sigf(o1) * tanh_fast(sigf(f1) * hv1 + sigf(i1) * tanh_fast(h1));
                        *(float2*)(outNH + (size_t)(rbase + r) * 256 + j0) = nh;
                    }
                #pragma unroll
                for (int m = 0; m < 2; ++m)
                    #pragma unroll
                    for (int n = 0; n < 4; ++n)
                        #pragma unroll
                        for (int c = 0; c < 4; ++c) acc[m][n][c] = 0.0f;
            } else {
                // ---- logits epilogue: log_softmax over 256 cols ----
                float* redm = (float*)(smem + SM_REDM);
                float* reds = (float*)(smem + SM_REDS);

                #pragma unroll
                for (int mt = 0; mt < 2; ++mt)
                    #pragma unroll
                    for (int nt = 0; nt < 4; ++nt) {
                        int n0 = wn * 32 + nt * 8 + lq * 2;
                        acc[mt][nt][0] += bias[1024 + n0];
                        acc[mt][nt][1] += bias[1024 + n0 + 1];
                        acc[mt][nt][2] += bias[1024 + n0];
                        acc[mt][nt][3] += bias[1024 + n0 + 1];
                    }

                #pragma unroll
                for (int mt = 0; mt < 2; ++mt)
                    #pragma unroll
                    for (int rh = 0; rh < 2; ++rh) {
                        float m = -3.4e38f;
                        #pragma unroll
                        for (int nt = 0; nt < 4; ++nt) {
                            m = fmaxf(m, acc[mt][nt][rh*2]);
                            m = fmaxf(m, acc[mt][nt][rh*2+1]);
                        }
                        m = fmaxf(m, __shfl_xor_sync(0xffffffffu, m, 1));
                        m = fmaxf(m, __shfl_xor_sync(0xffffffffu, m, 2));
                        if (lq == 0) {
                            int r = wm * 32 + mt * 16 + rh * 8 + gID;
                            redm[r * 8 + wn] = m;
                        }
                    }
                __syncthreads();

                float M[2][2], L[2][2];
                #pragma unroll
                for (int mt = 0; mt < 2; ++mt)
                    #pragma unroll
                    for (int rh = 0; rh < 2; ++rh) {
                        int r = wm * 32 + mt * 16 + rh * 8 + gID;
                        const float* rm = redm + r * 8;
                        float m = fmaxf(fmaxf(fmaxf(rm[0], rm[1]),
                                              fmaxf(rm[2], rm[3])),
                                        fmaxf(fmaxf(rm[4], rm[5]),
                                              fmaxf(rm[6], rm[7])));
                        M[mt][rh] = m;
                        float s = 0.0f;
                        #pragma unroll
                        for (int nt = 0; nt < 4; ++nt) {
                            s += __expf(acc[mt][nt][rh*2]   - m);
                            s += __expf(acc[mt][nt][rh*2+1] - m);
                        }
                        s += __shfl_xor_sync(0xffffffffu, s, 1);
                        s += __shfl_xor_sync(0xffffffffu, s, 2);
                        if (lq == 0) reds[r * 8 + wn] = s;
                    }
                __syncthreads();

                #pragma unroll
                for (int mt = 0; mt < 2; ++mt)
                    #pragma unroll
                    for (int rh = 0; rh < 2; ++rh) {
                        int r = wm * 32 + mt * 16 + rh * 8 + gID;
                        const float* rs = reds + r * 8;
                        float st = ((rs[0] + rs[1]) + (rs[2] + rs[3])) +
                                   ((rs[4] + rs[5]) + (rs[6] + rs[7]));
                        L[mt][rh] = M[mt][rh] + logf(st);
                    }

                #pragma unroll
                for (int mt = 0; mt < 2; ++mt)
                    #pragma unroll
                    for (int rh = 0; rh < 2; ++rh) {
                        int r = wm * 32 + mt * 16 + rh * 8 + gID;
                        float lse = L[mt][rh];
                        #pragma unroll
                        for (int nt = 0; nt < 4; ++nt) {
                            int n0 = wn * 32 + nt * 8 + lq * 2;
                            float2 o;
                            o.x = acc[mt][nt][rh*2]   - lse;
                            o.y = acc[mt][nt][rh*2+1] - lse;
                            *(float2*)(outLS + (size_t)(rbase + r) * 256 + n0) = o;
                        }
                    }
            }
        }
        __syncthreads();   // all warps done with this W buffer before reuse
    }
}

extern "C" void kernel_launch(void* const* d_in, const int* in_sizes, int n_in,
                              void* d_out, int out_size)
{
    (void)in_sizes; (void)n_in; (void)out_size;
    const float* input  = (const float*)d_in[0];
    const float* hidden = (const float*)d_in[1];
    const float* w_i2h  = (const float*)d_in[2];
    const float* b_i2h  = (const float*)d_in[3];
    const float* w_i2o  = (const float*)d_in[4];
    const float* b_i2o  = (const float*)d_in[5];
    float* out = (float*)d_out;

    repack_kernel<<<(NTILES * TILE_U32 + 255) / 256, 256>>>(w_i2h, w_i2o);

    cudaFuncSetAttribute(lstm_mma_kernel,
                         cudaFuncAttributeMaxDynamicSharedMemorySize,
                         SMEM_TOTAL);
    lstm_mma_kernel<<<BATCH / MT, THREADS, SMEM_TOTAL>>>(
        input, hidden, b_i2h, b_i2o, out);
}

// round 10
// speedup vs baseline: 1.7237x; 1.2085x over previous
#include <cuda_runtime.h>
#include <cuda_fp16.h>
#include <cstdint>
#include <math.h>

// LSTM_2370821948014 — round 9: R8 (fp16 mma + ldmatrix + 96-k tiles) with
// corrected ldmatrix B quadrant addressing (R8 NaN root cause: matrix 2/3
// lanes addressed rows +16/+32 instead of +8/+24 -> out-of-tile reads).
//
// 20 tiles of 256 rows x 96 k fp16 (48KB), NBUF=3, prefetch distance 2.
// 16 warps (2M x 8N), warp tile 32x32, mma.sync.m16n8k16.f16, fragments via
// ldmatrix.m8n8.x4 (A and B conflict-free under XOR swizzle).

static constexpr int BATCH = 65536;
static constexpr int ODIM  = 256;
static constexpr int KDIM  = 384;
static constexpr int MT    = 64;
static constexpr int THREADS = 512;
static constexpr int NBUF = 3;
static constexpr int NTILES  = 20;         // 5 chunks x 4 k-tiles
static constexpr int TILE_U32 = 12288;     // 256 rows x 48 words (48KB)

// SMEM layout (bytes)
static constexpr int PA2     = 196;                 // A pitch (u32, fp16 pairs)
static constexpr int SM_A    = 0;                   // 64*196*4 = 50176
static constexpr int SM_W    = 50176;               // 3 x 49152
static constexpr int WB      = 49152;
static constexpr int SM_BIAS = SM_W + NBUF * WB;    // 197632 (1280 floats)
static constexpr int SM_REDM = SM_BIAS + 5120;      // 202752
static constexpr int SM_REDS = SM_REDM + 2048;      // 204800
static constexpr int SM_MB   = SM_REDS + 2048;      // 206848
static constexpr int SMEM_TOTAL = SM_MB + 32;       // 206880

__device__ uint32_t w_packed[NTILES * TILE_U32];    // ~0.98MB scratch

// ---------------- helpers ----------------

__device__ __forceinline__ uint32_t smem_u32(const void* p) {
    uint32_t a;
    asm("{ .reg .u64 t; cvta.to.shared.u64 t, %1; cvt.u32.u64 %0, t; }"
        : "=r"(a) : "l"(p));
    return a;
}

__device__ __forceinline__ uint32_t pack_h2(float x, float y) {
    __half2 h = __floats2half2_rn(x, y);
    return *reinterpret_cast<uint32_t*>(&h);
}

__device__ __forceinline__ void mbar_init(uint32_t a) {
    asm volatile("mbarrier.init.shared.b64 [%0], %1;" :: "r"(a), "r"(1u) : "memory");
}

__device__ __forceinline__ void mbar_expect_tx(uint32_t a, uint32_t bytes) {
    asm volatile("mbarrier.arrive.expect_tx.shared.b64 _, [%0], %1;"
                 :: "r"(a), "r"(bytes) : "memory");
}

__device__ __forceinline__ void mbar_wait(uint32_t a, uint32_t parity) {
    asm volatile(
        "{\n\t"
        ".reg .pred P;\n\t"
        "W%=:\n\t"
        "mbarrier.try_wait.parity.acquire.cta.shared::cta.b64 P, [%0], %1, 0x989680;\n\t"
        "@P bra D%=;\n\t"
        "bra W%=;\n\t"
        "D%=:\n\t"
        "}"
        :: "r"(a), "r"(parity) : "memory");
}

__device__ __forceinline__ void bulk_ld(uint32_t dst, const void* src,
                                        uint32_t bytes, uint32_t mbar) {
    asm volatile(
        "cp.async.bulk.shared::cluster.global.mbarrier::complete_tx::bytes "
        "[%0], [%1], %2, [%3];"
        :: "r"(dst), "l"(src), "r"(bytes), "r"(mbar) : "memory");
}

__device__ __forceinline__ void ldsm4(uint32_t* r, uint32_t addr) {
    asm volatile(
        "ldmatrix.sync.aligned.m8n8.x4.shared.b16 {%0,%1,%2,%3}, [%4];"
        : "=r"(r[0]), "=r"(r[1]), "=r"(r[2]), "=r"(r[3]) : "r"(addr));
}

__device__ __forceinline__ void mma16(float* d, const uint32_t* a,
                                      uint32_t b0, uint32_t b1) {
    asm volatile(
        "mma.sync.aligned.m16n8k16.row.col.f32.f16.f16.f32 "
        "{%0,%1,%2,%3}, {%4,%5,%6,%7}, {%8,%9}, {%0,%1,%2,%3};"
        : "+f"(d[0]), "+f"(d[1]), "+f"(d[2]), "+f"(d[3])
        : "r"(a[0]), "r"(a[1]), "r"(a[2]), "r"(a[3]), "r"(b0), "r"(b1));
}

__device__ __forceinline__ float sigf(float x) {
    return 1.0f / (1.0f + __expf(-x));
}
__device__ __forceinline__ float tanh_fast(float x) {
    x = fminf(fmaxf(x, -15.0f), 15.0f);
    float e = __expf(2.0f * x);
    return (e - 1.0f) / (e + 1.0f);
}

// ---------------- repack kernel ----------------
// tile t = chunk*4 + kt.  Gates chunks (0..3): tile row v = wn*32 + g*8 + jlo
//   -> w_i2h row g*256 + chunk*64 + wn*8 + jlo.  Logits chunk (4): row v.
// Word w (0..47) of row v holds fp16 pair (k = kt*96 + 2w, +1), stored at
//   u32 index v*48 + (w ^ (((v>>1)&3)<<2)).

__global__ void repack_kernel(const float* __restrict__ w_i2h,
                              const float* __restrict__ w_i2o)
{
    int i = blockIdx.x * 256 + threadIdx.x;
    if (i >= NTILES * TILE_U32) return;
    int t  = i / TILE_U32;
    int e  = i - t * TILE_U32;
    int v  = e / 48;
    int w  = e - v * 48;
    int chunk = t >> 2;
    int kt    = t & 3;
    const float* src;
    int row;
    if (chunk < 4) {
        int wn  = v >> 5;
        int g   = (v >> 3) & 3;
        int jlo = v & 7;
        row = g * 256 + chunk * 64 + wn * 8 + jlo;
        src = w_i2h;
    } else {
        row = v;
        src = w_i2o;
    }
    const float* p = src + (size_t)row * KDIM + kt * 96 + w * 2;
    w_packed[t * TILE_U32 + v * 48 + (w ^ (((v >> 1) & 3) << 2))] =
        pack_h2(p[0], p[1]);
}

// ---------------- main kernel ----------------

__global__ __launch_bounds__(THREADS, 1)
void lstm_mma_kernel(const float* __restrict__ input,
                     const float* __restrict__ hidden,
                     const float* __restrict__ b_i2h,
                     const float* __restrict__ b_i2o,
                     float* __restrict__ out)
{
    extern __shared__ char smem[];
    const uint32_t sbase = smem_u32(smem);
    const int tid  = threadIdx.x;
    const int wid  = tid >> 5;
    const int lane = tid & 31;
    const int wm   = wid >> 3;          // 0..1 (M)
    const int wn   = wid & 7;           // 0..7 (N)
    const int gID  = lane >> 2;         // 0..7
    const int lq   = lane & 3;          // 0..3
    const int rbase = blockIdx.x * MT;

    uint32_t* Au2 = (uint32_t*)(smem + SM_A);
    float*    bias = (float*)(smem + SM_BIAS);

    // ldmatrix A: matrix q (lanes 8q..8q+7): rows +8*(q&1), k-half (q>>1)
    const int aRow  = wm * 32 + (lane & 7) + 8 * ((lane >> 3) & 1);
    const int aKsel = 4 * ((lane >> 4) & 1);           // 16B chunk (k0/k8)
    const uint32_t aBase0 = sbase + SM_A + (uint32_t)(aRow * PA2 + aKsel) * 4;
    const uint32_t aBase1 = aBase0 + 16 * PA2 * 4;

    // ldmatrix B: matrix q: nt-pair row (+8 if q>=2), k-half (q&1)
    //   lanes 0-7: (nt_even, k0); 8-15: (nt_even, k8);
    //   16-23: (nt_odd, k0); 24-31: (nt_odd, k8)
    const int bKb   = (lane >> 3) & 1;                 // k-half select
    const int bRow0 = wn * 32 + 8 * ((lane >> 4) & 1) + (lane & 7);  // nt {0,1}
    const int bRow1 = bRow0 + 16;                                    // nt {2,3}
    const int bMask0 = (bRow0 >> 1) & 3;
    const int bMask1 = (bRow1 >> 1) & 3;
    const uint32_t bOff0 = (uint32_t)bRow0 * 192;      // bytes within tile
    const uint32_t bOff1 = (uint32_t)bRow1 * 192;

    if (tid == 0)
        for (int b = 0; b < NBUF; ++b) mbar_init(sbase + SM_MB + 8 * b);
    __syncthreads();

    // prologue: issue tiles 0,1 (overlaps A/bias staging)
    if (tid == 0) {
        mbar_expect_tx(sbase + SM_MB, WB);
        bulk_ld(sbase + SM_W, w_packed, WB, sbase + SM_MB);
        mbar_expect_tx(sbase + SM_MB + 8, WB);
        bulk_ld(sbase + SM_W + WB, w_packed + TILE_U32, WB, sbase + SM_MB + 8);
    }

    // stage A (fp16 pairs, pitch 196 u32)
    for (int idx = tid; idx < MT * 96; idx += THREADS) {
        int r  = idx / 96;
        int c4 = idx - r * 96;
        float4 v = (c4 < 32)
            ? *(const float4*)(input  + (size_t)(rbase + r) * 128 + c4 * 4)
            : *(const float4*)(hidden + (size_t)(rbase + r) * 256 + (c4 - 32) * 4);
        uint2 u;
        u.x = pack_h2(v.x, v.y);
        u.y = pack_h2(v.z, v.w);
        *(uint2*)(Au2 + r * PA2 + c4 * 2) = u;
    }
    for (int i = tid; i < 1280; i += THREADS)
        bias[i] = (i < 1024) ? b_i2h[i] : b_i2o[i - 1024];
    __syncthreads();

    float* outLS = out;
    float* outNH = out + (size_t)BATCH * ODIM;

    float acc[2][4][4];
    #pragma unroll
    for (int m = 0; m < 2; ++m)
        #pragma unroll
        for (int n = 0; n < 4; ++n)
            #pragma unroll
            for (int c = 0; c < 4; ++c) acc[m][n][c] = 0.0f;

    for (int t = 0; t < NTILES; ++t) {
        const int buf = t % NBUF;
        if (t + 2 < NTILES && tid == 0) {
            int nb = (t + 2) % NBUF;
            uint32_t mb = sbase + SM_MB + 8 * nb;
            mbar_expect_tx(mb, WB);
            bulk_ld(sbase + SM_W + nb * WB,
                    w_packed + (size_t)(t + 2) * TILE_U32, WB, mb);
        }
        mbar_wait(sbase + SM_MB + 8 * buf, (t / NBUF) & 1);

        const uint32_t Wbase = sbase + SM_W + buf * WB;
        const uint32_t aK = (uint32_t)((t & 3) * 48) * 4;   // A word base (bytes)

        #pragma unroll
        for (int ks = 0; ks < 6; ++ks) {
            uint32_t a0[4], a1[4], b[8];
            const uint32_t aoff = aK + ks * 32;
            ldsm4(a0, aBase0 + aoff);
            ldsm4(a1, aBase1 + aoff);
            const uint32_t c0 = (uint32_t)(((2 * ks + bKb) ^ bMask0) << 4);
            const uint32_t c1 = (uint32_t)(((2 * ks + bKb) ^ bMask1) << 4);
            ldsm4(b + 0, Wbase + bOff0 + c0);    // nt 0 (k0,k8), nt 1 (k0,k8)
            ldsm4(b + 4, Wbase + bOff1 + c1);    // nt 2, nt 3
            mma16(acc[0][0], a0, b[0], b[1]);
            mma16(acc[1][0], a1, b[0], b[1]);
            mma16(acc[0][1], a0, b[2], b[3]);
            mma16(acc[1][1], a1, b[2], b[3]);
            mma16(acc[0][2], a0, b[4], b[5]);
            mma16(acc[1][2], a1, b[4], b[5]);
            mma16(acc[0][3], a0, b[6], b[7]);
            mma16(acc[1][3], a1, b[6], b[7]);
        }

        if ((t & 3) == 3) {
            const int chunk = t >> 2;
            if (chunk < 4) {
                // ---- LSTM epilogue: gates g = nt, all in-register ----
                #pragma unroll
                for (int mt = 0; mt < 2; ++mt)
                    #pragma unroll
                    for (int rh = 0; rh < 2; ++rh) {
                        int r  = wm * 32 + mt * 16 + rh * 8 + gID;
                        int j0 = chunk * 64 + wn * 8 + lq * 2;
                        int ci = rh * 2;
                        float h0 = acc[mt][0][ci]   + bias[j0];
                        float h1 = acc[mt][0][ci+1] + bias[j0+1];
                        float i0 = acc[mt][1][ci]   + bias[256+j0];
                        float i1 = acc[mt][1][ci+1] + bias[256+j0+1];
                        float f0 = acc[mt][2][ci]   + bias[512+j0];
                        float f1 = acc[mt][2][ci+1] + bias[512+j0+1];
                        float o0 = acc[mt][3][ci]   + bias[768+j0];
                        float o1 = acc[mt][3][ci+1] + bias[768+j0+1];
                        float2 hv = *(const float2*)(
                            hidden + (size_t)(rbase + r) * 256 + j0);
                        float2 nh;
                        nh.x = sigf(o0) * tanh_fast(sigf(f0) * hv.x + sigf(i0) * tanh_fast(h0));
                        nh.y = sigf(o1) * tanh_fast(sigf(f1) * hv.y + sigf(i1) * tanh_fast(h1));
                        *(float2*)(outNH + (size_t)(rbase + r) * 256 + j0) = nh;
                    }
                #pragma unroll
                for (int m = 0; m < 2; ++m)
                    #pragma unroll
                    for (int n = 0; n < 4; ++n)
                        #pragma unroll
                        for (int c = 0; c < 4; ++c) acc[m][n][c] = 0.0f;
            } else {
                // ---- logits epilogue: log_softmax over 256 cols ----
                float* redm = (float*)(smem + SM_REDM);
                float* reds = (float*)(smem + SM_REDS);

                #pragma unroll
                for (int mt = 0; mt < 2; ++mt)
                    #pragma unroll
                    for (int nt = 0; nt < 4; ++nt) {
                        int n0 = wn * 32 + nt * 8 + lq * 2;
                        acc[mt][nt][0] += bias[1024 + n0];
                        acc[mt][nt][1] += bias[1024 + n0 + 1];
                        acc[mt][nt][2] += bias[1024 + n0];
                        acc[mt][nt][3] += bias[1024 + n0 + 1];
                    }

                #pragma unroll
                for (int mt = 0; mt < 2; ++mt)
                    #pragma unroll
                    for (int rh = 0; rh < 2; ++rh) {
                        float m = -3.4e38f;
                        #pragma unroll
                        for (int nt = 0; nt < 4; ++nt) {
                            m = fmaxf(m, acc[mt][nt][rh*2]);
                            m = fmaxf(m, acc[mt][nt][rh*2+1]);
                        }
                        m = fmaxf(m, __shfl_xor_sync(0xffffffffu, m, 1));
                        m = fmaxf(m, __shfl_xor_sync(0xffffffffu, m, 2));
                        if (lq == 0) {
                            int r = wm * 32 + mt * 16 + rh * 8 + gID;
                            redm[r * 8 + wn] = m;
                        }
                    }
                __syncthreads();

                float M[2][2], L[2][2];
                #pragma unroll
                for (int mt = 0; mt < 2; ++mt)
                    #pragma unroll
                    for (int rh = 0; rh < 2; ++rh) {
                        int r = wm * 32 + mt * 16 + rh * 8 + gID;
                        const float* rm = redm + r * 8;
                        float m = fmaxf(fmaxf(fmaxf(rm[0], rm[1]),
                                              fmaxf(rm[2], rm[3])),
                                        fmaxf(fmaxf(rm[4], rm[5]),
                                              fmaxf(rm[6], rm[7])));
                        M[mt][rh] = m;
                        float s = 0.0f;
                        #pragma unroll
                        for (int nt = 0; nt < 4; ++nt) {
                            s += __expf(acc[mt][nt][rh*2]   - m);
                            s += __expf(acc[mt][nt][rh*2+1] - m);
                        }
                        s += __shfl_xor_sync(0xffffffffu, s, 1);
                        s += __shfl_xor_sync(0xffffffffu, s, 2);
                        if (lq == 0) reds[r * 8 + wn] = s;
                    }
                __syncthreads();

                #pragma unroll
                for (int mt = 0; mt < 2; ++mt)
                    #pragma unroll
                    for (int rh = 0; rh < 2; ++rh) {
                        int r = wm * 32 + mt * 16 + rh * 8 + gID;
                        const float* rs = reds + r * 8;
                        float st = ((rs[0] + rs[1]) + (rs[2] + rs[3])) +
                                   ((rs[4] + rs[5]) + (rs[6] + rs[7]));
                        L[mt][rh] = M[mt][rh] + logf(st);
                    }

                #pragma unroll
                for (int mt = 0; mt < 2; ++mt)
                    #pragma unroll
                    for (int rh = 0; rh < 2; ++rh) {
                        int r = wm * 32 + mt * 16 + rh * 8 + gID;
                        float lse = L[mt][rh];
                        #pragma unroll
                        for (int nt = 0; nt < 4; ++nt) {
                            int n0 = wn * 32 + nt * 8 + lq * 2;
                            float2 o;
                            o.x = acc[mt][nt][rh*2]   - lse;
                            o.y = acc[mt][nt][rh*2+1] - lse;
                            *(float2*)(outLS + (size_t)(rbase + r) * 256 + n0) = o;
                        }
                    }
            }
        }
        __syncthreads();   // all warps done with this W buffer before reuse
    }
}

extern "C" void kernel_launch(void* const* d_in, const int* in_sizes, int n_in,
                              void* d_out, int out_size)
{
    (void)in_sizes; (void)n_in; (void)out_size;
    const float* input  = (const float*)d_in[0];
    const float* hidden = (const float*)d_in[1];
    const float* w_i2h  = (const float*)d_in[2];
    const float* b_i2h  = (const float*)d_in[3];
    const float* w_i2o  = (const float*)d_in[4];
    const float* b_i2o  = (const float*)d_in[5];
    float* out = (float*)d_out;

    repack_kernel<<<(NTILES * TILE_U32 + 255) / 256, 256>>>(w_i2h, w_i2o);

    cudaFuncSetAttribute(lstm_mma_kernel,
                         cudaFuncAttributeMaxDynamicSharedMemorySize,
                         SMEM_TOTAL);
    lstm_mma_kernel<<<BATCH / MT, THREADS, SMEM_TOTAL>>>(
        input, hidden, b_i2h, b_i2o, out);
}

// round 11
// speedup vs baseline: 1.9000x; 1.1022x over previous
#include <cuda_runtime.h>
#include <cuda_fp16.h>
#include <cstdint>
#include <math.h>

// LSTM_2370821948014 — round 10: MT=128 rows/CTA (512 CTAs), fp16 mma +
// ldmatrix, 20 tiles of 256 rows x 96 k (48KB), NBUF=2.
// 16 warps as 4M x 4N, warp tile 32x64 (acc[2][8][4]).
// Halves W L2 traffic, halves per-work overhead, cuts crossbar/MMA 25%.

static constexpr int BATCH = 65536;
static constexpr int ODIM  = 256;
static constexpr int KDIM  = 384;
static constexpr int MT    = 128;
static constexpr int THREADS = 512;
static constexpr int NBUF = 2;
static constexpr int NTILES  = 20;         // 5 chunks x 4 k-tiles
static constexpr int TILE_U32 = 12288;     // 256 rows x 48 words (48KB)

// SMEM layout (bytes)
static constexpr int PA2     = 196;                 // A pitch (u32, fp16 pairs)
static constexpr int SM_A    = 0;                   // 128*196*4 = 100352
static constexpr int SM_W    = 100352;              // 2 x 49152
static constexpr int WB      = 49152;
static constexpr int SM_BIAS = SM_W + NBUF * WB;    // 198656 (1280 floats)
static constexpr int SM_REDM = SM_BIAS + 5120;      // 203776 (512 floats)
static constexpr int SM_REDS = SM_REDM + 2048;      // 205824
static constexpr int SM_MB   = SM_REDS + 2048;      // 207872
static constexpr int SMEM_TOTAL = SM_MB + 32;       // 207904

__device__ uint32_t w_packed[NTILES * TILE_U32];    // ~0.98MB scratch

// ---------------- helpers ----------------

__device__ __forceinline__ uint32_t smem_u32(const void* p) {
    uint32_t a;
    asm("{ .reg .u64 t; cvta.to.shared.u64 t, %1; cvt.u32.u64 %0, t; }"
        : "=r"(a) : "l"(p));
    return a;
}

__device__ __forceinline__ uint32_t pack_h2(float x, float y) {
    __half2 h = __floats2half2_rn(x, y);
    return *reinterpret_cast<uint32_t*>(&h);
}

__device__ __forceinline__ void mbar_init(uint32_t a) {
    asm volatile("mbarrier.init.shared.b64 [%0], %1;" :: "r"(a), "r"(1u) : "memory");
}

__device__ __forceinline__ void mbar_expect_tx(uint32_t a, uint32_t bytes) {
    asm volatile("mbarrier.arrive.expect_tx.shared.b64 _, [%0], %1;"
                 :: "r"(a), "r"(bytes) : "memory");
}

__device__ __forceinline__ void mbar_wait(uint32_t a, uint32_t parity) {
    asm volatile(
        "{\n\t"
        ".reg .pred P;\n\t"
        "W%=:\n\t"
        "mbarrier.try_wait.parity.acquire.cta.shared::cta.b64 P, [%0], %1, 0x989680;\n\t"
        "@P bra D%=;\n\t"
        "bra W%=;\n\t"
        "D%=:\n\t"
        "}"
        :: "r"(a), "r"(parity) : "memory");
}

__device__ __forceinline__ void bulk_ld(uint32_t dst, const void* src,
                                        uint32_t bytes, uint32_t mbar) {
    asm volatile(
        "cp.async.bulk.shared::cluster.global.mbarrier::complete_tx::bytes "
        "[%0], [%1], %2, [%3];"
        :: "r"(dst), "l"(src), "r"(bytes), "r"(mbar) : "memory");
}

__device__ __forceinline__ void ldsm4(uint32_t* r, uint32_t addr) {
    asm volatile(
        "ldmatrix.sync.aligned.m8n8.x4.shared.b16 {%0,%1,%2,%3}, [%4];"
        : "=r"(r[0]), "=r"(r[1]), "=r"(r[2]), "=r"(r[3]) : "r"(addr));
}

__device__ __forceinline__ void mma16(float* d, const uint32_t* a,
                                      uint32_t b0, uint32_t b1) {
    asm volatile(
        "mma.sync.aligned.m16n8k16.row.col.f32.f16.f16.f32 "
        "{%0,%1,%2,%3}, {%4,%5,%6,%7}, {%8,%9}, {%0,%1,%2,%3};"
        : "+f"(d[0]), "+f"(d[1]), "+f"(d[2]), "+f"(d[3])
        : "r"(a[0]), "r"(a[1]), "r"(a[2]), "r"(a[3]), "r"(b0), "r"(b1));
}

__device__ __forceinline__ float sigf(float x) {
    return 1.0f / (1.0f + __expf(-x));
}
__device__ __forceinline__ float tanh_fast(float x) {
    x = fminf(fmaxf(x, -15.0f), 15.0f);
    float e = __expf(2.0f * x);
    return (e - 1.0f) / (e + 1.0f);
}

// ---------------- repack kernel ----------------
// tile t = chunk*4 + kt.  Gates chunks (0..3): tile row
//   v = wn*64 + (g*2+jh)*8 + jlo  ->  w_i2h row g*256 + chunk*64 + wn*16 +
//   jh*8 + jlo   (wn 0..3; all 4 gates of (r,j) in one thread).
// Logits chunk (4): row v -> w_i2o row v.
// Word w (0..47) of row v holds fp16 pair (k = kt*96 + 2w, +1), at u32 index
//   v*48 + (w ^ (((v>>1)&3)<<2)).

__global__ void repack_kernel(const float* __restrict__ w_i2h,
                              const float* __restrict__ w_i2o)
{
    int i = blockIdx.x * 256 + threadIdx.x;
    if (i >= NTILES * TILE_U32) return;
    int t  = i / TILE_U32;
    int e  = i - t * TILE_U32;
    int v  = e / 48;
    int w  = e - v * 48;
    int chunk = t >> 2;
    int kt    = t & 3;
    const float* src;
    int row;
    if (chunk < 4) {
        int wn  = v >> 6;
        int nt  = (v >> 3) & 7;
        int jlo = v & 7;
        int g   = nt >> 1;
        int jh  = nt & 1;
        row = g * 256 + chunk * 64 + wn * 16 + jh * 8 + jlo;
        src = w_i2h;
    } else {
        row = v;
        src = w_i2o;
    }
    const float* p = src + (size_t)row * KDIM + kt * 96 + w * 2;
    w_packed[t * TILE_U32 + v * 48 + (w ^ (((v >> 1) & 3) << 2))] =
        pack_h2(p[0], p[1]);
}

// ---------------- main kernel ----------------

__global__ __launch_bounds__(THREADS, 1)
void lstm_mma_kernel(const float* __restrict__ input,
                     const float* __restrict__ hidden,
                     const float* __restrict__ b_i2h,
                     const float* __restrict__ b_i2o,
                     float* __restrict__ out)
{
    extern __shared__ char smem[];
    const uint32_t sbase = smem_u32(smem);
    const int tid  = threadIdx.x;
    const int wid  = tid >> 5;
    const int lane = tid & 31;
    const int wm   = wid >> 2;          // 0..3 (M)
    const int wn   = wid & 3;           // 0..3 (N)
    const int gID  = lane >> 2;         // 0..7
    const int lq   = lane & 3;          // 0..3
    const int rbase = blockIdx.x * MT;

    uint32_t* Au2 = (uint32_t*)(smem + SM_A);
    float*    bias = (float*)(smem + SM_BIAS);

    // ldmatrix A: matrix q (lanes 8q..8q+7): rows +8*(q&1), k-half (q>>1)
    const int aRow  = wm * 32 + (lane & 7) + 8 * ((lane >> 3) & 1);
    const int aKsel = 4 * ((lane >> 4) & 1);           // 16B chunk (k0/k8)
    const uint32_t aBase0 = sbase + SM_A + (uint32_t)(aRow * PA2 + aKsel) * 4;
    const uint32_t aBase1 = aBase0 + 16 * PA2 * 4;

    // ldmatrix B: pair p covers nt {2p,2p+1}; rows bRowBase + 16p.
    //   lanes 0-7:(nt_e,k0) 8-15:(nt_e,k8) 16-23:(nt_o,k0) 24-31:(nt_o,k8)
    const int bKb     = (lane >> 3) & 1;
    const int bRowBase = wn * 64 + 8 * ((lane >> 4) & 1) + (lane & 7);
    const int bMask   = (bRowBase >> 1) & 3;   // +16p doesn't change bits 1-2
    const uint32_t bOff0 = (uint32_t)bRowBase * 192;
    const uint32_t bOff1 = bOff0 + 16 * 192;
    const uint32_t bOff2 = bOff0 + 32 * 192;
    const uint32_t bOff3 = bOff0 + 48 * 192;

    if (tid == 0)
        for (int b = 0; b < NBUF; ++b) mbar_init(sbase + SM_MB + 8 * b);
    __syncthreads();

    // prologue: issue tile 0 (overlaps A/bias staging)
    if (tid == 0) {
        mbar_expect_tx(sbase + SM_MB, WB);
        bulk_ld(sbase + SM_W, w_packed, WB, sbase + SM_MB);
    }

    // stage A (fp16 pairs, pitch 196 u32)
    for (int idx = tid; idx < MT * 96; idx += THREADS) {
        int r  = idx / 96;
        int c4 = idx - r * 96;
        float4 v = (c4 < 32)
            ? *(const float4*)(input  + (size_t)(rbase + r) * 128 + c4 * 4)
            : *(const float4*)(hidden + (size_t)(rbase + r) * 256 + (c4 - 32) * 4);
        uint2 u;
        u.x = pack_h2(v.x, v.y);
        u.y = pack_h2(v.z, v.w);
        *(uint2*)(Au2 + r * PA2 + c4 * 2) = u;
    }
    for (int i = tid; i < 1280; i += THREADS)
        bias[i] = (i < 1024) ? b_i2h[i] : b_i2o[i - 1024];
    __syncthreads();

    float* outLS = out;
    float* outNH = out + (size_t)BATCH * ODIM;

    float acc[2][8][4];
    #pragma unroll
    for (int m = 0; m < 2; ++m)
        #pragma unroll
        for (int n = 0; n < 8; ++n)
            #pragma unroll
            for (int c = 0; c < 4; ++c) acc[m][n][c] = 0.0f;

    for (int t = 0; t < NTILES; ++t) {
        const int buf = t & 1;
        // prefetch t+1 into other buffer (its consumer t-1 retired at the
        // previous __syncthreads)
        if (t + 1 < NTILES && tid == 0) {
            int nb = buf ^ 1;
            uint32_t mb = sbase + SM_MB + 8 * nb;
            mbar_expect_tx(mb, WB);
            bulk_ld(sbase + SM_W + nb * WB,
                    w_packed + (size_t)(t + 1) * TILE_U32, WB, mb);
        }
        mbar_wait(sbase + SM_MB + 8 * buf, (t >> 1) & 1);

        const uint32_t Wbase = sbase + SM_W + buf * WB;
        const uint32_t aK = (uint32_t)((t & 3) * 48) * 4;   // A byte base

        #pragma unroll
        for (int ks = 0; ks < 6; ++ks) {
            uint32_t a0[4], a1[4], b[16];
            const uint32_t aoff = aK + ks * 32;
            ldsm4(a0, aBase0 + aoff);
            ldsm4(a1, aBase1 + aoff);
            const uint32_t c = (uint32_t)(((2 * ks + bKb) ^ bMask) << 4);
            ldsm4(b + 0,  Wbase + bOff0 + c);   // nt 0,1
            ldsm4(b + 4,  Wbase + bOff1 + c);   // nt 2,3
            ldsm4(b + 8,  Wbase + bOff2 + c);   // nt 4,5
            ldsm4(b + 12, Wbase + bOff3 + c);   // nt 6,7
            #pragma unroll
            for (int p = 0; p < 4; ++p) {
                mma16(acc[0][2*p],   a0, b[4*p],   b[4*p+1]);
                mma16(acc[1][2*p],   a1, b[4*p],   b[4*p+1]);
                mma16(acc[0][2*p+1], a0, b[4*p+2], b[4*p+3]);
                mma16(acc[1][2*p+1], a1, b[4*p+2], b[4*p+3]);
            }
        }

        if ((t & 3) == 3) {
            const int chunk = t >> 2;
            if (chunk < 4) {
                // ---- LSTM epilogue: nt = g*2+jh, all gates in-register ----
                #pragma unroll
                for (int mt = 0; mt < 2; ++mt)
                    #pragma unroll
                    for (int rh = 0; rh < 2; ++rh)
                        #pragma unroll
                        for (int jh = 0; jh < 2; ++jh) {
                            int r  = wm * 32 + mt * 16 + rh * 8 + gID;
                            int j0 = chunk * 64 + wn * 16 + jh * 8 + lq * 2;
                            int ci = rh * 2;
                            float h0 = acc[mt][jh][ci]     + bias[j0];
                            float h1 = acc[mt][jh][ci+1]   + bias[j0+1];
                            float i0 = acc[mt][2+jh][ci]   + bias[256+j0];
                            float i1 = acc[mt][2+jh][ci+1] + bias[256+j0+1];
                            float f0 = acc[mt][4+jh][ci]   + bias[512+j0];
                            float f1 = acc[mt][4+jh][ci+1] + bias[512+j0+1];
                            float o0 = acc[mt][6+jh][ci]   + bias[768+j0];
                            float o1 = acc[mt][6+jh][ci+1] + bias[768+j0+1];
                            float2 hv = *(const float2*)(
                                hidden + (size_t)(rbase + r) * 256 + j0);
                            float2 nh;
                            nh.x = sigf(o0) * tanh_fast(sigf(f0) * hv.x + sigf(i0) * tanh_fast(h0));
                            nh.y = sigf(o1) * tanh_fast(sigf(f1) * hv.y + sigf(i1) * tanh_fast(h1));
                            *(float2*)(outNH + (size_t)(rbase + r) * 256 + j0) = nh;
                        }
                #pragma unroll
                for (int m = 0; m < 2; ++m)
                    #pragma unroll
                    for (int n = 0; n < 8; ++n)
                        #pragma unroll
                        for (int c = 0; c < 4; ++c) acc[m][n][c] = 0.0f;
            } else {
                // ---- logits epilogue: log_softmax over 256 cols ----
                float* redm = (float*)(smem + SM_REDM);
                float* reds = (float*)(smem + SM_REDS);

                #pragma unroll
                for (int mt = 0; mt < 2; ++mt)
                    #pragma unroll
                    for (int nt = 0; nt < 8; ++nt) {
                        int n0 = wn * 64 + nt * 8 + lq * 2;
                        acc[mt][nt][0] += bias[1024 + n0];
                        acc[mt][nt][1] += bias[1024 + n0 + 1];
                        acc[mt][nt][2] += bias[1024 + n0];
                        acc[mt][nt][3] += bias[1024 + n0 + 1];
                    }

                #pragma unroll
                for (int mt = 0; mt < 2; ++mt)
                    #pragma unroll
                    for (int rh = 0; rh < 2; ++rh) {
                        float m = -3.4e38f;
                        #pragma unroll
                        for (int nt = 0; nt < 8; ++nt) {
                            m = fmaxf(m, acc[mt][nt][rh*2]);
                            m = fmaxf(m, acc[mt][nt][rh*2+1]);
                        }
                        m = fmaxf(m, __shfl_xor_sync(0xffffffffu, m, 1));
                        m = fmaxf(m, __shfl_xor_sync(0xffffffffu, m, 2));
                        if (lq == 0) {
                            int r = wm * 32 + mt * 16 + rh * 8 + gID;
                            redm[r * 4 + wn] = m;
                        }
                    }
                __syncthreads();

                float M[2][2], L[2][2];
                #pragma unroll
                for (int mt = 0; mt < 2; ++mt)
                    #pragma unroll
                    for (int rh = 0; rh < 2; ++rh) {
                        int r = wm * 32 + mt * 16 + rh * 8 + gID;
                        const float* rm = redm + r * 4;
                        float m = fmaxf(fmaxf(rm[0], rm[1]),
                                        fmaxf(rm[2], rm[3]));
                        M[mt][rh] = m;
                        float s = 0.0f;
                        #pragma unroll
                        for (int nt = 0; nt < 8; ++nt) {
                            s += __expf(acc[mt][nt][rh*2]   - m);
                            s += __expf(acc[mt][nt][rh*2+1] - m);
                        }
                        s += __shfl_xor_sync(0xffffffffu, s, 1);
                        s += __shfl_xor_sync(0xffffffffu, s, 2);
                        if (lq == 0) reds[r * 4 + wn] = s;
                    }
                __syncthreads();

                #pragma unroll
                for (int mt = 0; mt < 2; ++mt)
                    #pragma unroll
                    for (int rh = 0; rh < 2; ++rh) {
                        int r = wm * 32 + mt * 16 + rh * 8 + gID;
                        const float* rs = reds + r * 4;
                        float st = (rs[0] + rs[1]) + (rs[2] + rs[3]);
                        L[mt][rh] = M[mt][rh] + logf(st);
                    }

                #pragma unroll
                for (int mt = 0; mt < 2; ++mt)
                    #pragma unroll
                    for (int rh = 0; rh < 2; ++rh) {
                        int r = wm * 32 + mt * 16 + rh * 8 + gID;
                        float lse = L[mt][rh];
                        #pragma unroll
                        for (int nt = 0; nt < 8; ++nt) {
                            int n0 = wn * 64 + nt * 8 + lq * 2;
                            float2 o;
                            o.x = acc[mt][nt][rh*2]   - lse;
                            o.y = acc[mt][nt][rh*2+1] - lse;
                            *(float2*)(outLS + (size_t)(rbase + r) * 256 + n0) = o;
                        }
                    }
            }
        }
        __syncthreads();   // all warps done with this W buffer before reuse
    }
}

extern "C" void kernel_launch(void* const* d_in, const int* in_sizes, int n_in,
                              void* d_out, int out_size)
{
    (void)in_sizes; (void)n_in; (void)out_size;
    const float* input  = (const float*)d_in[0];
    const float* hidden = (const float*)d_in[1];
    const float* w_i2h  = (const float*)d_in[2];
    const float* b_i2h  = (const float*)d_in[3];
    const float* w_i2o  = (const float*)d_in[4];
    const float* b_i2o  = (const float*)d_in[5];
    float* out = (float*)d_out;

    repack_kernel<<<(NTILES * TILE_U32 + 255) / 256, 256>>>(w_i2h, w_i2o);

    cudaFuncSetAttribute(lstm_mma_kernel,
                         cudaFuncAttributeMaxDynamicSharedMemorySize,
                         SMEM_TOTAL);
    lstm_mma_kernel<<<BATCH / MT, THREADS, SMEM_TOTAL>>>(
        input, hidden, b_i2h, b_i2o, out);
}

// round 12
// speedup vs baseline: 1.9471x; 1.0248x over previous
#include <cuda_runtime.h>
#include <cuda_fp16.h>
#include <cstdint>
#include <math.h>

// LSTM_2370821948014 — round 11: desynchronized warps. No per-tile CTA
// barriers: full[3] (tx mbarriers) + cons[3] (count=16 mbarriers, one arrive
// per warp) protect the W ring; warps drift and interleave LDSM/MMA phases.
// MT=128 rows/CTA (512 CTAs), 30 tiles of 256 rows x 64 k fp16 (32KB),
// NBUF=3. 16 warps as 4M x 4N, warp tile 32x64, mma.sync.m16n8k16.f16 via
// ldmatrix.m8n8.x4. B swizzle: 16B-chunk index ^= (row & 7) (conflict-free
// at 128B row stride).

static constexpr int BATCH = 65536;
static constexpr int ODIM  = 256;
static constexpr int KDIM  = 384;
static constexpr int MT    = 128;
static constexpr int THREADS = 512;
static constexpr int NBUF = 3;
static constexpr int NTILES  = 30;        // 5 chunks x 6 k-tiles (k=64)
static constexpr int TILE_U32 = 8192;     // 256 rows x 32 words (32KB)

// SMEM layout (bytes)
static constexpr int PA2     = 196;                 // A pitch (u32, fp16 pairs)
static constexpr int SM_A    = 0;                   // 128*196*4 = 100352
static constexpr int SM_W    = 100352;              // 3 x 32768
static constexpr int WB      = 32768;
static constexpr int SM_BIAS = SM_W + NBUF * WB;    // 198656 (1280 floats)
static constexpr int SM_REDM = SM_BIAS + 5120;      // 203776
static constexpr int SM_REDS = SM_REDM + 2048;      // 205824
static constexpr int SM_MB   = SM_REDS + 2048;      // 207872: full[3] cons[3]
static constexpr int SMEM_TOTAL = SM_MB + 64;       // 207936

__device__ uint32_t w_packed[NTILES * TILE_U32];    // ~0.98MB scratch

// ---------------- helpers ----------------

__device__ __forceinline__ uint32_t smem_u32(const void* p) {
    uint32_t a;
    asm("{ .reg .u64 t; cvta.to.shared.u64 t, %1; cvt.u32.u64 %0, t; }"
        : "=r"(a) : "l"(p));
    return a;
}

__device__ __forceinline__ uint32_t pack_h2(float x, float y) {
    __half2 h = __floats2half2_rn(x, y);
    return *reinterpret_cast<uint32_t*>(&h);
}

__device__ __forceinline__ void mbar_init(uint32_t a, uint32_t cnt) {
    asm volatile("mbarrier.init.shared.b64 [%0], %1;" :: "r"(a), "r"(cnt) : "memory");
}

__device__ __forceinline__ void mbar_expect_tx(uint32_t a, uint32_t bytes) {
    asm volatile("mbarrier.arrive.expect_tx.shared.b64 _, [%0], %1;"
                 :: "r"(a), "r"(bytes) : "memory");
}

__device__ __forceinline__ void mbar_arrive(uint32_t a) {
    asm volatile("mbarrier.arrive.shared.b64 _, [%0];" :: "r"(a) : "memory");
}

__device__ __forceinline__ void mbar_wait(uint32_t a, uint32_t parity) {
    asm volatile(
        "{\n\t"
        ".reg .pred P;\n\t"
        "W%=:\n\t"
        "mbarrier.try_wait.parity.acquire.cta.shared::cta.b64 P, [%0], %1, 0x989680;\n\t"
        "@P bra D%=;\n\t"
        "bra W%=;\n\t"
        "D%=:\n\t"
        "}"
        :: "r"(a), "r"(parity) : "memory");
}

__device__ __forceinline__ void bulk_ld(uint32_t dst, const void* src,
                                        uint32_t bytes, uint32_t mbar) {
    asm volatile(
        "cp.async.bulk.shared::cluster.global.mbarrier::complete_tx::bytes "
        "[%0], [%1], %2, [%3];"
        :: "r"(dst), "l"(src), "r"(bytes), "r"(mbar) : "memory");
}

__device__ __forceinline__ void ldsm4(uint32_t* r, uint32_t addr) {
    asm volatile(
        "ldmatrix.sync.aligned.m8n8.x4.shared.b16 {%0,%1,%2,%3}, [%4];"
        : "=r"(r[0]), "=r"(r[1]), "=r"(r[2]), "=r"(r[3]) : "r"(addr));
}

__device__ __forceinline__ void mma16(float* d, const uint32_t* a,
                                      uint32_t b0, uint32_t b1) {
    asm volatile(
        "mma.sync.aligned.m16n8k16.row.col.f32.f16.f16.f32 "
        "{%0,%1,%2,%3}, {%4,%5,%6,%7}, {%8,%9}, {%0,%1,%2,%3};"
        : "+f"(d[0]), "+f"(d[1]), "+f"(d[2]), "+f"(d[3])
        : "r"(a[0]), "r"(a[1]), "r"(a[2]), "r"(a[3]), "r"(b0), "r"(b1));
}

__device__ __forceinline__ float sigf(float x) {
    return 1.0f / (1.0f + __expf(-x));
}
__device__ __forceinline__ float tanh_fast(float x) {
    x = fminf(fmaxf(x, -15.0f), 15.0f);
    float e = __expf(2.0f * x);
    return (e - 1.0f) / (e + 1.0f);
}

// ---------------- repack kernel ----------------
// tile t = chunk*6 + kt (k window 64).  Gates chunks (0..3): tile row
//   v = wn*64 + (g*2+jh)*8 + jlo -> w_i2h row g*256 + chunk*64 + wn*16 +
//   jh*8 + jlo.  Logits chunk (4): row v -> w_i2o row v.
// Row v holds 32 fp16-pair words (k = kt*64 + 2w). 16B-chunk swizzle:
//   stored u32 index = v*32 + (((w>>2) ^ (v&7)) << 2) + (w&3).

__global__ void repack_kernel(const float* __restrict__ w_i2h,
                              const float* __restrict__ w_i2o)
{
    int i = blockIdx.x * 256 + threadIdx.x;
    if (i >= NTILES * TILE_U32) return;
    int t  = i / TILE_U32;
    int e  = i - t * TILE_U32;
    int v  = e >> 5;
    int w  = e & 31;
    int chunk = t / 6;
    int kt    = t - chunk * 6;
    const float* src;
    int row;
    if (chunk < 4) {
        int wn  = v >> 6;
        int nt  = (v >> 3) & 7;
        int jlo = v & 7;
        int g   = nt >> 1;
        int jh  = nt & 1;
        row = g * 256 + chunk * 64 + wn * 16 + jh * 8 + jlo;
        src = w_i2h;
    } else {
        row = v;
        src = w_i2o;
    }
    const float* p = src + (size_t)row * KDIM + kt * 64 + w * 2;
    w_packed[t * TILE_U32 + v * 32 + (((w >> 2) ^ (v & 7)) << 2) + (w & 3)] =
        pack_h2(p[0], p[1]);
}

// ---------------- main kernel ----------------

__global__ __launch_bounds__(THREADS, 1)
void lstm_mma_kernel(const float* __restrict__ input,
                     const float* __restrict__ hidden,
                     const float* __restrict__ b_i2h,
                     const float* __restrict__ b_i2o,
                     float* __restrict__ out)
{
    extern __shared__ char smem[];
    const uint32_t sbase = smem_u32(smem);
    const int tid  = threadIdx.x;
    const int wid  = tid >> 5;
    const int lane = tid & 31;
    const int wm   = wid >> 2;          // 0..3 (M)
    const int wn   = wid & 3;           // 0..3 (N)
    const int gID  = lane >> 2;         // 0..7
    const int lq   = lane & 3;          // 0..3
    const int rbase = blockIdx.x * MT;
    const bool isProd = (tid == 0);

    uint32_t* Au2 = (uint32_t*)(smem + SM_A);
    float*    bias = (float*)(smem + SM_BIAS);
    const uint32_t fullB = sbase + SM_MB;        // 3 x 8B
    const uint32_t consB = sbase + SM_MB + 24;   // 3 x 8B

    // ldmatrix A: matrix q (lanes 8q..8q+7): rows +8*(q&1), k-half (q>>1)
    const int aRow  = wm * 32 + (lane & 7) + 8 * ((lane >> 3) & 1);
    const int aKsel = 4 * ((lane >> 4) & 1);           // 16B chunk (k0/k8)
    const uint32_t aBase0 = sbase + SM_A + (uint32_t)(aRow * PA2 + aKsel) * 4;
    const uint32_t aBase1 = aBase0 + 16 * PA2 * 4;

    // ldmatrix B: pair p covers nt {2p,2p+1}; rows bRowBase + 16p.
    const int bKb      = (lane >> 3) & 1;
    const int bRowBase = wn * 64 + 8 * ((lane >> 4) & 1) + (lane & 7);
    const int bMask    = bRowBase & 7;     // +16p,+8 keep (row&7)
    const uint32_t bOff0 = (uint32_t)bRowBase * 128;
    const uint32_t bOff1 = bOff0 + 16 * 128;
    const uint32_t bOff2 = bOff0 + 32 * 128;
    const uint32_t bOff3 = bOff0 + 48 * 128;

    if (tid == 0) {
        for (int b = 0; b < NBUF; ++b) {
            mbar_init(fullB + 8 * b, 1);
            mbar_init(consB + 8 * b, 16);
        }
    }
    __syncthreads();

    // prologue: load tiles 0,1,2 (overlaps A/bias staging)
    if (isProd) {
        for (int u = 0; u < NBUF; ++u) {
            mbar_expect_tx(fullB + 8 * u, WB);
            bulk_ld(sbase + SM_W + u * WB, w_packed + (size_t)u * TILE_U32,
                    WB, fullB + 8 * u);
        }
    }

    // stage A (fp16 pairs, pitch 196 u32)
    for (int idx = tid; idx < MT * 96; idx += THREADS) {
        int r  = idx / 96;
        int c4 = idx - r * 96;
        float4 v = (c4 < 32)
            ? *(const float4*)(input  + (size_t)(rbase + r) * 128 + c4 * 4)
            : *(const float4*)(hidden + (size_t)(rbase + r) * 256 + (c4 - 32) * 4);
        uint2 u;
        u.x = pack_h2(v.x, v.y);
        u.y = pack_h2(v.z, v.w);
        *(uint2*)(Au2 + r * PA2 + c4 * 2) = u;
    }
    for (int i = tid; i < 1280; i += THREADS)
        bias[i] = (i < 1024) ? b_i2h[i] : b_i2o[i - 1024];
    __syncthreads();   // A/bias visible to all warps before fragment reads

    float* outLS = out;
    float* outNH = out + (size_t)BATCH * ODIM;

    float acc[2][8][4];
    #pragma unroll
    for (int m = 0; m < 2; ++m)
        #pragma unroll
        for (int n = 0; n < 8; ++n)
            #pragma unroll
            for (int c = 0; c < 4; ++c) acc[m][n][c] = 0.0f;

    for (int t = 0; t < NTILES; ++t) {
        const int buf = t % NBUF;
        mbar_wait(fullB + 8 * buf, (t / NBUF) & 1);

        const uint32_t Wbase = sbase + SM_W + buf * WB;
        const uint32_t aK = (uint32_t)((t % 6) * 128);   // A byte base (k=64)

        #pragma unroll
        for (int ks = 0; ks < 4; ++ks) {
            uint32_t a0[4], a1[4], b[16];
            const uint32_t aoff = aK + ks * 32;
            ldsm4(a0, aBase0 + aoff);
            ldsm4(a1, aBase1 + aoff);
            const uint32_t c = (uint32_t)(((2 * ks + bKb) ^ bMask) << 4);
            ldsm4(b + 0,  Wbase + bOff0 + c);   // nt 0,1
            ldsm4(b + 4,  Wbase + bOff1 + c);   // nt 2,3
            ldsm4(b + 8,  Wbase + bOff2 + c);   // nt 4,5
            ldsm4(b + 12, Wbase + bOff3 + c);   // nt 6,7
            #pragma unroll
            for (int p = 0; p < 4; ++p) {
                mma16(acc[0][2*p],   a0, b[4*p],   b[4*p+1]);
                mma16(acc[1][2*p],   a1, b[4*p],   b[4*p+1]);
                mma16(acc[0][2*p+1], a0, b[4*p+2], b[4*p+3]);
                mma16(acc[1][2*p+1], a1, b[4*p+2], b[4*p+3]);
            }
        }

        // this warp is done with buffer buf
        if (lane == 0) mbar_arrive(consB + 8 * buf);

        // producer: once ALL warps have consumed tile t, reload buf for t+3
        if (isProd && t + NBUF < NTILES) {
            mbar_wait(consB + 8 * buf, (t / NBUF) & 1);
            mbar_expect_tx(fullB + 8 * buf, WB);
            bulk_ld(sbase + SM_W + buf * WB,
                    w_packed + (size_t)(t + NBUF) * TILE_U32, WB,
                    fullB + 8 * buf);
        }

        if ((t % 6) == 5) {
            const int chunk = t / 6;
            if (chunk < 4) {
                // ---- LSTM epilogue: nt = g*2+jh, all gates in-register ----
                #pragma unroll
                for (int mt = 0; mt < 2; ++mt)
                    #pragma unroll
                    for (int rh = 0; rh < 2; ++rh)
                        #pragma unroll
                        for (int jh = 0; jh < 2; ++jh) {
                            int r  = wm * 32 + mt * 16 + rh * 8 + gID;
                            int j0 = chunk * 64 + wn * 16 + jh * 8 + lq * 2;
                            int ci = rh * 2;
                            float h0 = acc[mt][jh][ci]     + bias[j0];
                            float h1 = acc[mt][jh][ci+1]   + bias[j0+1];
                            float i0 = acc[mt][2+jh][ci]   + bias[256+j0];
                            float i1 = acc[mt][2+jh][ci+1] + bias[256+j0+1];
                            float f0 = acc[mt][4+jh][ci]   + bias[512+j0];
                            float f1 = acc[mt][4+jh][ci+1] + bias[512+j0+1];
                            float o0 = acc[mt][6+jh][ci]   + bias[768+j0];
                            float o1 = acc[mt][6+jh][ci+1] + bias[768+j0+1];
                            float2 hv = *(const float2*)(
                                hidden + (size_t)(rbase + r) * 256 + j0);
                            float2 nh;
                            nh.x = sigf(o0) * tanh_fast(sigf(f0) * hv.x + sigf(i0) * tanh_fast(h0));
                            nh.y = sigf(o1) * tanh_fast(sigf(f1) * hv.y + sigf(i1) * tanh_fast(h1));
                            *(float2*)(outNH + (size_t)(rbase + r) * 256 + j0) = nh;
                        }
                #pragma unroll
                for (int m = 0; m < 2; ++m)
                    #pragma unroll
                    for (int n = 0; n < 8; ++n)
                        #pragma unroll
                        for (int c = 0; c < 4; ++c) acc[m][n][c] = 0.0f;
            } else {
                // ---- logits epilogue: log_softmax over 256 cols ----
                float* redm = (float*)(smem + SM_REDM);
                float* reds = (float*)(smem + SM_REDS);

                #pragma unroll
                for (int mt = 0; mt < 2; ++mt)
                    #pragma unroll
                    for (int nt = 0; nt < 8; ++nt) {
                        int n0 = wn * 64 + nt * 8 + lq * 2;
                        acc[mt][nt][0] += bias[1024 + n0];
                        acc[mt][nt][1] += bias[1024 + n0 + 1];
                        acc[mt][nt][2] += bias[1024 + n0];
                        acc[mt][nt][3] += bias[1024 + n0 + 1];
                    }

                #pragma unroll
                for (int mt = 0; mt < 2; ++mt)
                    #pragma unroll
                    for (int rh = 0; rh < 2; ++rh) {
                        float m = -3.4e38f;
                        #pragma unroll
                        for (int nt = 0; nt < 8; ++nt) {
                            m = fmaxf(m, acc[mt][nt][rh*2]);
                            m = fmaxf(m, acc[mt][nt][rh*2+1]);
                        }
                        m = fmaxf(m, __shfl_xor_sync(0xffffffffu, m, 1));
                        m = fmaxf(m, __shfl_xor_sync(0xffffffffu, m, 2));
                        if (lq == 0) {
                            int r = wm * 32 + mt * 16 + rh * 8 + gID;
                            redm[r * 4 + wn] = m;
                        }
                    }
                __syncthreads();

                float M[2][2], L[2][2];
                #pragma unroll
                for (int mt = 0; mt < 2; ++mt)
                    #pragma unroll
                    for (int rh = 0; rh < 2; ++rh) {
                        int r = wm * 32 + mt * 16 + rh * 8 + gID;
                        const float* rm = redm + r * 4;
                        float m = fmaxf(fmaxf(rm[0], rm[1]),
                                        fmaxf(rm[2], rm[3]));
                        M[mt][rh] = m;
                        float s = 0.0f;
                        #pragma unroll
                        for (int nt = 0; nt < 8; ++nt) {
                            s += __expf(acc[mt][nt][rh*2]   - m);
                            s += __expf(acc[mt][nt][rh*2+1] - m);
                        }
                        s += __shfl_xor_sync(0xffffffffu, s, 1);
                        s += __shfl_xor_sync(0xffffffffu, s, 2);
                        if (lq == 0) reds[r * 4 + wn] = s;
                    }
                __syncthreads();

                #pragma unroll
                for (int mt = 0; mt < 2; ++mt)
                    #pragma unroll
                    for (int rh = 0; rh < 2; ++rh) {
                        int r = wm * 32 + mt * 16 + rh * 8 + gID;
                        const float* rs = reds + r * 4;
                        float st = (rs[0] + rs[1]) + (rs[2] + rs[3]);
                        L[mt][rh] = M[mt][rh] + logf(st);
                    }

                #pragma unroll
                for (int mt = 0; mt < 2; ++mt)
                    #pragma unroll
                    for (int rh = 0; rh < 2; ++rh) {
                        int r = wm * 32 + mt * 16 + rh * 8 + gID;
                        float lse = L[mt][rh];
                        #pragma unroll
                        for (int nt = 0; nt < 8; ++nt) {
                            int n0 = wn * 64 + nt * 8 + lq * 2;
                            float2 o;
                            o.x = acc[mt][nt][rh*2]   - lse;
                            o.y = acc[mt][nt][rh*2+1] - lse;
                            *(float2*)(outLS + (size_t)(rbase + r) * 256 + n0) = o;
                        }
                    }
            }
        }
    }
}

extern "C" void kernel_launch(void* const* d_in, const int* in_sizes, int n_in,
                              void* d_out, int out_size)
{
    (void)in_sizes; (void)n_in; (void)out_size;
    const float* input  = (const float*)d_in[0];
    const float* hidden = (const float*)d_in[1];
    const float* w_i2h  = (const float*)d_in[2];
    const float* b_i2h  = (const float*)d_in[3];
    const float* w_i2o  = (const float*)d_in[4];
    const float* b_i2o  = (const float*)d_in[5];
    float* out = (float*)d_out;

    repack_kernel<<<(NTILES * TILE_U32 + 255) / 256, 256>>>(w_i2h, w_i2o);

    cudaFuncSetAttribute(lstm_mma_kernel,
                         cudaFuncAttributeMaxDynamicSharedMemorySize,
                         SMEM_TOTAL);
    lstm_mma_kernel<<<BATCH / MT, THREADS, SMEM_TOTAL>>>(
        input, hidden, b_i2h, b_i2o, out);
}